// round 17
// baseline (speedup 1.0000x reference)
#include <cuda_runtime.h>
#include <math.h>
#include <stdint.h>

#define NB   128
#define LQ   32
#define LDOC 180
#define DIM  128
#define NW   8

#define NTHR  256

// dynamic SMEM byte offsets (fp32 doc tile, 512B rows, 16B-chunk swizzle)
#define OFF_D     0                    // 180*512 = 92160
#define OFF_Q     92160                // 32*512 = 16384 (fp32/tf32 scaled queries)
#define OFF_SSQ   OFF_Q                // overlay: ssq consumed before Q written
#define OFF_INVD  108544               // 128 floats
#define OFF_INVQ  109056               // 32 floats
#define OFF_SMASK 109184               // 184 floats = 736
#define SM_BYTES  109920               // 2 CTAs/SM
#define OFF_WMAX  OFF_Q                // overlay after post-MMA sync

__device__ float    g_scores[NB * NW];
__device__ unsigned g_ticket = 0;

__device__ __forceinline__ uint32_t smem_u32(const void* p) {
    uint32_t a;
    asm("{ .reg .u64 t; cvta.to.shared.u64 t, %1; cvt.u32.u64 %0, t; }" : "=r"(a) : "l"(p));
    return a;
}

#define CP_ASYNC16(saddr, gptr) \
    asm volatile("cp.async.cg.shared.global [%0], [%1], 16;" :: "r"(saddr), "l"(gptr))
#define CP_COMMIT()  asm volatile("cp.async.commit_group;" ::: "memory")
#define CP_WAIT0()   asm volatile("cp.async.wait_group 0;" ::: "memory")

__device__ __forceinline__ void mma_tf32(float* c, const uint32_t* a, const uint32_t* b) {
    asm volatile(
        "mma.sync.aligned.m16n8k8.row.col.f32.tf32.tf32.f32 "
        "{%0,%1,%2,%3}, {%4,%5,%6,%7}, {%8,%9}, {%0,%1,%2,%3};"
        : "+f"(c[0]), "+f"(c[1]), "+f"(c[2]), "+f"(c[3])
        : "r"(a[0]), "r"(a[1]), "r"(a[2]), "r"(a[3]), "r"(b[0]), "r"(b[1]));
}

__device__ __forceinline__ uint32_t tf32_rna(float v) {
    uint32_t o;
    asm("cvt.rna.tf32.f32 %0, %1;" : "=r"(o) : "f"(v));
    return o;
}

// swizzled byte offset inside the [rows][512B] fp32 tile (16B chunk XOR row&7)
__device__ __forceinline__ uint32_t swz32(uint32_t row, uint32_t chunk) {
    return row * 512u + ((chunk ^ (row & 7u)) << 4);
}

__global__ void __launch_bounds__(NTHR, 2) maxsim_kernel(
    const float* __restrict__ qraw, const float* __restrict__ doc,
    const int* __restrict__ mask, const float* __restrict__ labels,
    float* __restrict__ out)
{
    extern __shared__ char smc[];
    const uint32_t smb = smem_u32(smc);
    float* ssq   = (float*)(smc + OFF_SSQ);
    float* sinvd = (float*)(smc + OFF_INVD);
    float* sinvq = (float*)(smc + OFF_INVQ);
    float* smask = (float*)(smc + OFF_SMASK);

    const int tid  = threadIdx.x;
    const int lane = tid & 31;
    const int w    = tid >> 5;           // 0..7
    const int bw   = blockIdx.x;
    const int b    = bw >> 3;

    // ---- issue the WHOLE doc slab as cp.async (register-free, 92KB in flight) ----
    {
        const char* gd = (const char*)(doc + (size_t)bw * LDOC * DIM);
        #pragma unroll
        for (int i = 0; i < 23; i++) {
            int idx = tid + i * NTHR;              // 16B chunk index, 5760 total
            if (idx < (LDOC * DIM * 4) / 16) {
                int row = idx >> 5, chunk = idx & 31;
                CP_ASYNC16(smb + OFF_D + swz32((uint32_t)row, (uint32_t)chunk),
                           gd + idx * 16);
            }
        }
        CP_COMMIT();
    }

    // ---- overlap the flight: mask -> smem, per-query inverse norms ----
    for (int l = tid; l < 184; l += NTHR)
        smask[l] = (l < LDOC && mask[bw * LDOC + l] != 0) ? 1.0f : 0.0f;
    {
        const float* qb = qraw + (size_t)b * LQ * DIM;
        #pragma unroll
        for (int k = 0; k < 4; k++) {
            int q = w * 4 + k;
            const float* qp = qb + q * DIM + lane;
            float a0 = qp[0], a1 = qp[32], a2 = qp[64], a3 = qp[96];
            float s = a0 * a0 + a1 * a1 + a2 * a2 + a3 * a3;
            #pragma unroll
            for (int o = 16; o; o >>= 1) s += __shfl_xor_sync(0xffffffffu, s, o);
            if (lane == 0) sinvq[q] = 1.0f / fmaxf(sqrtf(s), 1e-12f);
        }
    }

    CP_WAIT0();
    __syncthreads();                     // slab + mask visible to all

    // ---- per-feature masked sumsq from the fp32 tile ----
    {
        const int c = lane;              // logical chunk -> features 4c..4c+3
        float s0 = 0.f, s1 = 0.f, s2 = 0.f, s3 = 0.f;
        #pragma unroll 4
        for (int i = 0; i < 23; i++) {
            int row = w + 8 * i;
            if (row < LDOC) {
                float4 v = *(const float4*)(smc + OFF_D + swz32((uint32_t)row, (uint32_t)c));
                float mk = smask[row];
                s0 += mk * v.x * v.x; s1 += mk * v.y * v.y;
                s2 += mk * v.z * v.z; s3 += mk * v.w * v.w;
            }
        }
        *(float4*)&ssq[tid * 4] = make_float4(s0, s1, s2, s3);
    }
    __syncthreads();

    if (tid < DIM) {
        float s = 0.f;
        #pragma unroll
        for (int wp = 0; wp < 8; wp++) s += ssq[wp * 128 + tid];
        sinvd[tid] = 1.0f / fmaxf(sqrtf(s), 1e-12f);
    }
    __syncthreads();

    // ---- queries: scale by invq*invd, cvt to tf32, store swizzled (overwrites ssq) ----
    {
        int q = tid >> 3;
        int d0 = (tid & 7) * 16;
        const float* qp = qraw + (size_t)b * LQ * DIM + q * DIM;
        float sq = sinvq[q];
        #pragma unroll
        for (int i = 0; i < 4; i++) {
            int d = d0 + i * 4;
            float4 v = *(const float4*)(qp + d);
            uint4 t;
            t.x = tf32_rna(v.x * sq * sinvd[d]);
            t.y = tf32_rna(v.y * sq * sinvd[d + 1]);
            t.z = tf32_rna(v.z * sq * sinvd[d + 2]);
            t.w = tf32_rna(v.w * sq * sinvd[d + 3]);
            *(uint4*)(smc + OFF_Q + swz32((uint32_t)q, (uint32_t)(d >> 2))) = t;
        }
    }
    __syncthreads();

    // ---- TF32 MMA: warp = (N half nh) x (3 M-tiles of 16 rows) ----
    const int nh = w & 1;                // queries nh*16 .. nh*16+15
    const int mt = (w >> 1) * 3;
    int mstart[3];
    #pragma unroll
    for (int j = 0; j < 3; j++) {
        int r = (mt + j) * 16;
        mstart[j] = (r > 164) ? 164 : r; // clamp: last tile covers rows 164..179
    }
    const int grp  = lane >> 2;          // 0..7
    const int thr4 = lane & 3;

    float acc[3][2][4];
    #pragma unroll
    for (int m = 0; m < 3; m++)
        #pragma unroll
        for (int n = 0; n < 2; n++)
            #pragma unroll
            for (int j = 0; j < 4; j++) acc[m][n][j] = 0.f;

    #pragma unroll 4
    for (int ks = 0; ks < 16; ks++) {
        const uint32_t c0 = 2u * (uint32_t)ks;
        uint32_t bfr[4];
        #pragma unroll
        for (int n = 0; n < 2; n++) {
            uint32_t q = (uint32_t)(nh * 16 + n * 8 + grp);
            bfr[n * 2 + 0] = *(const uint32_t*)(smc + OFF_Q + swz32(q, c0)     + thr4 * 4);
            bfr[n * 2 + 1] = *(const uint32_t*)(smc + OFF_Q + swz32(q, c0 + 1) + thr4 * 4);
        }
        #pragma unroll
        for (int m = 0; m < 3; m++) {
            uint32_t r0 = (uint32_t)(mstart[m] + grp), r1 = r0 + 8u;
            uint32_t afr[4];
            afr[0] = *(const uint32_t*)(smc + OFF_D + swz32(r0, c0)     + thr4 * 4);
            afr[1] = *(const uint32_t*)(smc + OFF_D + swz32(r1, c0)     + thr4 * 4);
            afr[2] = *(const uint32_t*)(smc + OFF_D + swz32(r0, c0 + 1) + thr4 * 4);
            afr[3] = *(const uint32_t*)(smc + OFF_D + swz32(r1, c0 + 1) + thr4 * 4);
            mma_tf32(acc[m][0], afr, &bfr[0]);
            mma_tf32(acc[m][1], afr, &bfr[2]);
        }
    }

    // ---- apply row mask (masked/duplicate rows -> exactly 0, matching reference) ----
    #pragma unroll
    for (int m = 0; m < 3; m++) {
        float mr0 = smask[mstart[m] + grp];
        float mr1 = smask[mstart[m] + grp + 8];
        #pragma unroll
        for (int n = 0; n < 2; n++) {
            acc[m][n][0] *= mr0; acc[m][n][1] *= mr0;
            acc[m][n][2] *= mr1; acc[m][n][3] *= mr1;
        }
    }
    __syncthreads();                     // Q tile dead; warpmax overlays it

    float* warpmax = (float*)(smc + OFF_WMAX);   // [8 warps][16 cols]
    #pragma unroll
    for (int n = 0; n < 2; n++) {
        #pragma unroll
        for (int j = 0; j < 2; j++) {
            float mx = fmaxf(acc[0][n][j], acc[0][n][j + 2]);
            mx = fmaxf(mx, fmaxf(acc[1][n][j], acc[1][n][j + 2]));
            mx = fmaxf(mx, fmaxf(acc[2][n][j], acc[2][n][j + 2]));
            mx = fmaxf(mx, __shfl_xor_sync(0xffffffffu, mx, 4));
            mx = fmaxf(mx, __shfl_xor_sync(0xffffffffu, mx, 8));
            mx = fmaxf(mx, __shfl_xor_sync(0xffffffffu, mx, 16));
            if (lane < 4)
                warpmax[w * 16 + n * 8 + lane * 2 + j] = mx;
        }
    }
    __syncthreads();

    if (tid < 32) {
        int half = tid >> 4, c = tid & 15;
        float v = warpmax[(half)      * 16 + c];
        v = fmaxf(v, warpmax[(half + 2) * 16 + c]);
        v = fmaxf(v, warpmax[(half + 4) * 16 + c]);
        v = fmaxf(v, warpmax[(half + 6) * 16 + c]);
        #pragma unroll
        for (int o = 16; o; o >>= 1) v += __shfl_xor_sync(0xffffffffu, v, o);
        if (tid == 0) g_scores[bw] = v;
    }

    // ---- grid ticket: last block computes the KL loss ----
    __shared__ unsigned slast;
    if (tid == 0) {
        __threadfence();
        unsigned t = atomicAdd(&g_ticket, 1u);
        slast = (t == (unsigned)(NB * NW - 1)) ? 1u : 0u;
    }
    __syncthreads();
    if (slast) {
        if (tid == 0) g_ticket = 0;
        __threadfence();
        float accl = 0.f;
        if (tid < NB) {
            float s[NW], lab[NW];
            #pragma unroll
            for (int ww = 0; ww < NW; ww++) {
                s[ww]   = *((volatile float*)&g_scores[tid * NW + ww]);
                lab[ww] = labels[tid * NW + ww];
            }
            float m = s[0];
            #pragma unroll
            for (int ww = 1; ww < NW; ww++) m = fmaxf(m, s[ww]);
            float se = 0.f;
            #pragma unroll
            for (int ww = 0; ww < NW; ww++) se += expf(s[ww] - m);
            float lse = logf(se) + m;
            #pragma unroll
            for (int ww = 0; ww < NW; ww++)
                accl += expf(lab[ww]) * (lab[ww] - (s[ww] - lse));
        }
        #pragma unroll
        for (int o = 16; o; o >>= 1) accl += __shfl_xor_sync(0xffffffffu, accl, o);
        __shared__ float red2[8];
        if (lane == 0) red2[w] = accl;
        __syncthreads();
        if (tid == 0) {
            float t2 = 0.f;
            #pragma unroll
            for (int i = 0; i < 8; i++) t2 += red2[i];
            out[0] = t2 / (float)NB;
        }
    }
}

// ---------------- launch ----------------
extern "C" void kernel_launch(void* const* d_in, const int* in_sizes, int n_in,
                              void* d_out, int out_size) {
    const float* q      = (const float*)d_in[0];
    const float* doc    = (const float*)d_in[1];
    const int*   mask   = (const int*)d_in[2];
    const float* labels = (const float*)d_in[3];
    float* out = (float*)d_out;

    cudaFuncSetAttribute(maxsim_kernel,
                         cudaFuncAttributeMaxDynamicSharedMemorySize, SM_BYTES);

    maxsim_kernel<<<NB * NW, NTHR, SM_BYTES>>>(q, doc, mask, labels, out);
}